// round 1
// baseline (speedup 1.0000x reference)
#include <cuda_runtime.h>
#include <cuda_bf16.h>
#include <math.h>

// Problem constants
#define H_DIM     2048
#define NV        32
#define NK        16
#define DK        128
#define DV        128
#define CONV_K    4
#define KEY_DIM   2048            // NK*DK
#define VALUE_DIM 4096            // NV*DV
#define CONV_DIM  8192            // 2*KEY_DIM + VALUE_DIM
#define TOTAL_GEMV_ROWS (CONV_DIM + VALUE_DIM + NV + NV)   // 12352

// Scratch (allocation-free contract: __device__ globals)
__device__ float g_conv_out[CONV_DIM];
__device__ float g_z[VALUE_DIM];
__device__ float g_b[NV];
__device__ float g_a[NV];
__device__ float g_xn[VALUE_DIM];

__device__ __forceinline__ float warp_sum(float v) {
    #pragma unroll
    for (int o = 16; o; o >>= 1) v += __shfl_xor_sync(0xffffffffu, v, o);
    return v;
}

// ---------------------------------------------------------------------------
// Kernel A: fused input projections (qkv, z, b, a) + conv shift/silu epilogue.
// One warp per output row; x staged in shared memory.
// ---------------------------------------------------------------------------
__global__ void __launch_bounds__(256) k_gemv_conv(
    const float* __restrict__ x_in,
    const float* __restrict__ qkv_w,
    const float* __restrict__ z_w,
    const float* __restrict__ b_w,
    const float* __restrict__ a_w,
    const float* __restrict__ conv_state,
    const float* __restrict__ conv_w,
    float* __restrict__ out_conv_state)   // d_out + 2048
{
    __shared__ float xs[H_DIM];
    for (int i = threadIdx.x; i < H_DIM; i += blockDim.x) xs[i] = x_in[i];
    __syncthreads();

    const int warp = threadIdx.x >> 5;
    const int lane = threadIdx.x & 31;
    const int r = blockIdx.x * 8 + warp;
    if (r >= TOTAL_GEMV_ROWS) return;

    const float* w;
    if      (r < CONV_DIM)            w = qkv_w + (size_t)r * H_DIM;
    else if (r < CONV_DIM + VALUE_DIM) w = z_w  + (size_t)(r - CONV_DIM) * H_DIM;
    else if (r < CONV_DIM + VALUE_DIM + NV) w = b_w + (size_t)(r - CONV_DIM - VALUE_DIM) * H_DIM;
    else                              w = a_w  + (size_t)(r - CONV_DIM - VALUE_DIM - NV) * H_DIM;

    const float4* __restrict__ w4 = (const float4*)w;
    const float4* __restrict__ x4 = (const float4*)xs;
    float acc = 0.f;
    #pragma unroll 4
    for (int i = lane; i < H_DIM / 4; i += 32) {
        float4 a4 = w4[i];
        float4 b4 = x4[i];
        acc += a4.x * b4.x + a4.y * b4.y + a4.z * b4.z + a4.w * b4.w;
    }
    acc = warp_sum(acc);

    if (lane == 0) {
        if (r < CONV_DIM) {
            // conv: win = [cs1, cs2, cs3, mixed_qkv]; out = silu(win . conv_w)
            float cs1 = conv_state[r * 4 + 1];
            float cs2 = conv_state[r * 4 + 2];
            float cs3 = conv_state[r * 4 + 3];
            float c0 = conv_w[r * 4 + 0];
            float c1 = conv_w[r * 4 + 1];
            float c2 = conv_w[r * 4 + 2];
            float c3 = conv_w[r * 4 + 3];
            float s = cs1 * c0 + cs2 * c1 + cs3 * c2 + acc * c3;
            g_conv_out[r] = s / (1.f + expf(-s));
            float4 ncs = make_float4(cs1, cs2, cs3, acc);
            ((float4*)out_conv_state)[r] = ncs;
        } else if (r < CONV_DIM + VALUE_DIM) {
            g_z[r - CONV_DIM] = acc;
        } else if (r < CONV_DIM + VALUE_DIM + NV) {
            g_b[r - CONV_DIM - VALUE_DIM] = acc;
        } else {
            g_a[r - CONV_DIM - VALUE_DIM - NV] = acc;
        }
    }
}

// ---------------------------------------------------------------------------
// Kernel B: per-head delta rule. 32 blocks (one per NV head), 128 threads
// (one per v-column). Two passes over rec (2nd pass hits L2).
// ---------------------------------------------------------------------------
__global__ void __launch_bounds__(128) k_delta(
    const float* __restrict__ rec_in,
    const float* __restrict__ dt_bias,
    const float* __restrict__ A_log,
    const float* __restrict__ norm_w,
    float* __restrict__ rec_out)          // d_out + 2048 + 32768
{
    const int h = blockIdx.x;
    const int t = threadIdx.x;           // 0..127  == v column
    const int warp = t >> 5, lane = t & 31;
    const int kvh = h >> 1;              // vpk = NV/NK = 2

    __shared__ float qn[DK], kn[DK];
    __shared__ float rq[4], rk[4];
    __shared__ float s_gexp, s_beta;

    float qraw = g_conv_out[kvh * DK + t];
    float kraw = g_conv_out[KEY_DIM + kvh * DK + t];
    float vval = g_conv_out[2 * KEY_DIM + h * DV + t];

    float sq = warp_sum(qraw * qraw);
    float sk = warp_sum(kraw * kraw);
    if (lane == 0) { rq[warp] = sq; rk[warp] = sk; }
    __syncthreads();
    float sumq = rq[0] + rq[1] + rq[2] + rq[3];
    float sumk = rk[0] + rk[1] + rk[2] + rk[3];
    qn[t] = qraw * rsqrtf(sumq + 1e-6f) * 0.08838834764831845f;  // 1/sqrt(DK)
    kn[t] = kraw * rsqrtf(sumk + 1e-6f);

    if (t == 0) {
        float bv = g_b[h];
        float av = g_a[h] + dt_bias[h];
        float sp = (av > 20.f) ? av : log1pf(expf(av));
        float g  = -expf(A_log[h]) * sp;
        s_gexp = expf(g);
        s_beta = 1.f / (1.f + expf(-bv));
    }
    __syncthreads();
    const float gexp = s_gexp, beta = s_beta;

    const float* __restrict__ rh = rec_in  + (size_t)h * DK * DV;
    float*       __restrict__ ro = rec_out + (size_t)h * DK * DV;

    // Pass 1: kv_mem[v] = gexp * sum_k rec[k,v] * kn[k]
    float kv = 0.f;
    #pragma unroll 8
    for (int kk = 0; kk < DK; kk++) kv += rh[kk * DV + t] * kn[kk];
    kv *= gexp;
    const float dl = (vval - kv) * beta;

    // Pass 2: rec update + core accumulation
    float core = 0.f;
    #pragma unroll 8
    for (int kk = 0; kk < DK; kk++) {
        float rn = rh[kk * DV + t] * gexp + kn[kk] * dl;
        ro[kk * DV + t] = rn;
        core += rn * qn[kk];
    }

    // RMSNorm over DV + silu(z) gate
    float c2 = warp_sum(core * core);
    __syncthreads();                      // protect rq reuse
    if (lane == 0) rq[warp] = c2;
    __syncthreads();
    float var = (rq[0] + rq[1] + rq[2] + rq[3]) * (1.f / 128.f);
    float zv = g_z[h * DV + t];
    float xn = core * rsqrtf(var + 1e-6f) * norm_w[t] * (zv / (1.f + expf(-zv)));
    g_xn[h * DV + t] = xn;
}

// ---------------------------------------------------------------------------
// Kernel C: out_proj GEMV, 2048 rows x 4096 cols; warp per row.
// ---------------------------------------------------------------------------
__global__ void __launch_bounds__(256) k_outproj(
    const float* __restrict__ ow,
    float* __restrict__ out_hidden)
{
    __shared__ float vs[VALUE_DIM];
    for (int i = threadIdx.x; i < VALUE_DIM; i += blockDim.x) vs[i] = g_xn[i];
    __syncthreads();

    const int warp = threadIdx.x >> 5;
    const int lane = threadIdx.x & 31;
    const int r = blockIdx.x * 8 + warp;

    const float4* __restrict__ w4 = (const float4*)(ow + (size_t)r * VALUE_DIM);
    const float4* __restrict__ v4 = (const float4*)vs;
    float acc = 0.f;
    #pragma unroll 4
    for (int i = lane; i < VALUE_DIM / 4; i += 32) {
        float4 a4 = w4[i];
        float4 b4 = v4[i];
        acc += a4.x * b4.x + a4.y * b4.y + a4.z * b4.z + a4.w * b4.w;
    }
    acc = warp_sum(acc);
    if (lane == 0) out_hidden[r] = acc;
}

// ---------------------------------------------------------------------------
// Launch: outputs concatenated flat in reference return order:
//   hidden_out (2048) | new_conv_state (32768) | rec (524288)
// ---------------------------------------------------------------------------
extern "C" void kernel_launch(void* const* d_in, const int* in_sizes, int n_in,
                              void* d_out, int out_size) {
    const float* hidden_in  = (const float*)d_in[0];
    const float* conv_state = (const float*)d_in[1];
    const float* rec_state  = (const float*)d_in[2];
    const float* conv_w     = (const float*)d_in[3];
    const float* qkv_w      = (const float*)d_in[4];
    const float* z_w        = (const float*)d_in[5];
    const float* b_w        = (const float*)d_in[6];
    const float* a_w        = (const float*)d_in[7];
    const float* out_proj_w = (const float*)d_in[8];
    const float* dt_bias    = (const float*)d_in[9];
    const float* A_log      = (const float*)d_in[10];
    const float* norm_w     = (const float*)d_in[11];

    float* out        = (float*)d_out;
    float* out_hidden = out;
    float* out_cs     = out + H_DIM;
    float* out_rec    = out + H_DIM + CONV_DIM * CONV_K;

    // A: 12352 rows, 8 warps/block -> 1544 blocks
    k_gemv_conv<<<(TOTAL_GEMV_ROWS + 7) / 8, 256>>>(
        hidden_in, qkv_w, z_w, b_w, a_w, conv_state, conv_w, out_cs);

    // B: one block per value head
    k_delta<<<NV, 128>>>(rec_state, dt_bias, A_log, norm_w, out_rec);

    // C: 2048 rows, 8 warps/block -> 256 blocks
    k_outproj<<<H_DIM / 8, 256>>>(out_proj_w, out_hidden);
}

// round 2
// speedup vs baseline: 1.1923x; 1.1923x over previous
#include <cuda_runtime.h>
#include <cuda_bf16.h>
#include <math.h>

// Problem constants
#define H_DIM     2048
#define NV        32
#define NK        16
#define DK        128
#define DV        128
#define CONV_K    4
#define KEY_DIM   2048            // NK*DK
#define VALUE_DIM 4096            // NV*DV
#define CONV_DIM  8192            // 2*KEY_DIM + VALUE_DIM
#define TOTAL_GEMV_ROWS (CONV_DIM + VALUE_DIM + NV + NV)   // 12352

// Scratch (allocation-free contract: __device__ globals)
__device__ float g_conv_out[CONV_DIM];
__device__ float g_z[VALUE_DIM];
__device__ float g_b[NV];
__device__ float g_a[NV];
__device__ float g_xn[VALUE_DIM];

__device__ __forceinline__ float warp_sum(float v) {
    #pragma unroll
    for (int o = 16; o; o >>= 1) v += __shfl_xor_sync(0xffffffffu, v, o);
    return v;
}

// ---------------------------------------------------------------------------
// Kernel A: fused input projections (qkv, z, b, a) + conv shift/silu epilogue.
// One warp per output row; x staged in shared memory. Two independent
// accumulators over row halves + full unroll -> 16 float4 loads in flight.
// ---------------------------------------------------------------------------
__global__ void __launch_bounds__(256) k_gemv_conv(
    const float* __restrict__ x_in,
    const float* __restrict__ qkv_w,
    const float* __restrict__ z_w,
    const float* __restrict__ b_w,
    const float* __restrict__ a_w,
    const float* __restrict__ conv_state,
    const float* __restrict__ conv_w,
    float* __restrict__ out_conv_state)
{
    __shared__ float xs[H_DIM];
    for (int i = threadIdx.x; i < H_DIM; i += blockDim.x) xs[i] = x_in[i];
    __syncthreads();

    const int warp = threadIdx.x >> 5;
    const int lane = threadIdx.x & 31;
    const int r = blockIdx.x * 8 + warp;
    if (r >= TOTAL_GEMV_ROWS) return;

    const float* w;
    if      (r < CONV_DIM)                  w = qkv_w + (size_t)r * H_DIM;
    else if (r < CONV_DIM + VALUE_DIM)      w = z_w   + (size_t)(r - CONV_DIM) * H_DIM;
    else if (r < CONV_DIM + VALUE_DIM + NV) w = b_w   + (size_t)(r - CONV_DIM - VALUE_DIM) * H_DIM;
    else                                    w = a_w   + (size_t)(r - CONV_DIM - VALUE_DIM - NV) * H_DIM;

    const float4* __restrict__ w4 = (const float4*)w;
    const float4* __restrict__ x4 = (const float4*)xs;
    float acc0 = 0.f, acc1 = 0.f;
    // 512 float4 per row; two halves of 256, 8 iterations each, fully unrolled.
    #pragma unroll 8
    for (int i = lane; i < 256; i += 32) {
        float4 a0 = w4[i];
        float4 a1 = w4[i + 256];
        float4 b0 = x4[i];
        float4 b1 = x4[i + 256];
        acc0 += a0.x * b0.x + a0.y * b0.y + a0.z * b0.z + a0.w * b0.w;
        acc1 += a1.x * b1.x + a1.y * b1.y + a1.z * b1.z + a1.w * b1.w;
    }
    float acc = warp_sum(acc0 + acc1);

    if (lane == 0) {
        if (r < CONV_DIM) {
            float cs1 = conv_state[r * 4 + 1];
            float cs2 = conv_state[r * 4 + 2];
            float cs3 = conv_state[r * 4 + 3];
            float c0 = conv_w[r * 4 + 0];
            float c1 = conv_w[r * 4 + 1];
            float c2 = conv_w[r * 4 + 2];
            float c3 = conv_w[r * 4 + 3];
            float s = cs1 * c0 + cs2 * c1 + cs3 * c2 + acc * c3;
            g_conv_out[r] = s / (1.f + expf(-s));
            ((float4*)out_conv_state)[r] = make_float4(cs1, cs2, cs3, acc);
        } else if (r < CONV_DIM + VALUE_DIM) {
            g_z[r - CONV_DIM] = acc;
        } else if (r < CONV_DIM + VALUE_DIM + NV) {
            g_b[r - CONV_DIM - VALUE_DIM] = acc;
        } else {
            g_a[r - CONV_DIM - VALUE_DIM - NV] = acc;
        }
    }
}

// ---------------------------------------------------------------------------
// Kernel B: per-head delta rule. 32 blocks x 512 threads.
// tid = q*128 + t:  q in [0,4) = DK quarter, t in [0,128) = v column.
// Each thread handles 32 kk values -> 4x memory parallelism vs R1.
// ---------------------------------------------------------------------------
__global__ void __launch_bounds__(512) k_delta(
    const float* __restrict__ rec_in,
    const float* __restrict__ dt_bias,
    const float* __restrict__ A_log,
    const float* __restrict__ norm_w,
    float* __restrict__ rec_out)
{
    const int h    = blockIdx.x;
    const int tid  = threadIdx.x;
    const int q    = tid >> 7;            // kk quarter 0..3
    const int t    = tid & 127;           // v column / k index
    const int warp = tid >> 5, lane = tid & 31;

    __shared__ float qn[DK], kn[DK];
    __shared__ float red[16];             // per-warp partials
    __shared__ float kvp[4][DK];          // kv partials per quarter
    __shared__ float crp[4][DK];          // core partials per quarter
    __shared__ float s_gexp, s_beta;

    // q/k raw values depend only on t; every group holds the full 128.
    const int kvh = h >> 1;               // vpk = 2
    float qraw = g_conv_out[kvh * DK + t];
    float kraw = g_conv_out[KEY_DIM + kvh * DK + t];
    float vval = g_conv_out[2 * KEY_DIM + h * DV + t];

    // L2 norms: per-warp sums; each group's 4 warps cover all t.
    float sq = warp_sum(qraw * qraw);
    float sk = warp_sum(kraw * kraw);
    if (lane == 0) red[warp] = sq;
    if (tid == 0) {
        float bv = g_b[h];
        float av = g_a[h] + dt_bias[h];
        float sp = (av > 20.f) ? av : log1pf(expf(av));
        s_gexp = expf(-expf(A_log[h]) * sp);
        s_beta = 1.f / (1.f + expf(-bv));
    }
    __syncthreads();
    float sumq = red[q * 4 + 0] + red[q * 4 + 1] + red[q * 4 + 2] + red[q * 4 + 3];
    __syncthreads();
    if (lane == 0) red[warp] = sk;
    __syncthreads();
    float sumk = red[q * 4 + 0] + red[q * 4 + 1] + red[q * 4 + 2] + red[q * 4 + 3];
    if (q == 0) {
        qn[t] = qraw * rsqrtf(sumq + 1e-6f) * 0.08838834764831845f;  // 1/sqrt(DK)
        kn[t] = kraw * rsqrtf(sumk + 1e-6f);
    }
    __syncthreads();
    const float gexp = s_gexp, beta = s_beta;

    const float* __restrict__ rh = rec_in  + (size_t)h * DK * DV;
    float*       __restrict__ ro = rec_out + (size_t)h * DK * DV;
    const int kk0 = q * 32;

    // Pass 1: partial kv over this quarter's kk range.
    float kv = 0.f;
    #pragma unroll 8
    for (int j = 0; j < 32; j++) {
        int kk = kk0 + j;
        kv += rh[kk * DV + t] * kn[kk];
    }
    kvp[q][t] = kv;
    __syncthreads();
    float kvsum = (kvp[0][t] + kvp[1][t] + kvp[2][t] + kvp[3][t]) * gexp;
    const float dl = (vval - kvsum) * beta;

    // Pass 2: rec update (L2 hits) + partial core.
    float core = 0.f;
    #pragma unroll 8
    for (int j = 0; j < 32; j++) {
        int kk = kk0 + j;
        float rn = rh[kk * DV + t] * gexp + kn[kk] * dl;
        ro[kk * DV + t] = rn;
        core += rn * qn[kk];
    }
    crp[q][t] = core;
    __syncthreads();

    if (q == 0) {
        float c = crp[0][t] + crp[1][t] + crp[2][t] + crp[3][t];
        float c2 = warp_sum(c * c);
        if (lane == 0) red[warp] = c2;
        __syncthreads();
        float var = (red[0] + red[1] + red[2] + red[3]) * (1.f / 128.f);
        float zv = g_z[h * DV + t];
        g_xn[h * DV + t] = c * rsqrtf(var + 1e-6f) * norm_w[t]
                         * (zv / (1.f + expf(-zv)));
    }
}

// ---------------------------------------------------------------------------
// Kernel C: out_proj GEMV, 2048 rows x 4096 cols; warp per row, two
// accumulators over row halves for MLP.
// ---------------------------------------------------------------------------
__global__ void __launch_bounds__(256) k_outproj(
    const float* __restrict__ ow,
    float* __restrict__ out_hidden)
{
    __shared__ float vs[VALUE_DIM];
    for (int i = threadIdx.x; i < VALUE_DIM; i += blockDim.x) vs[i] = g_xn[i];
    __syncthreads();

    const int warp = threadIdx.x >> 5;
    const int lane = threadIdx.x & 31;
    const int r = blockIdx.x * 8 + warp;

    const float4* __restrict__ w4 = (const float4*)(ow + (size_t)r * VALUE_DIM);
    const float4* __restrict__ v4 = (const float4*)vs;
    float acc0 = 0.f, acc1 = 0.f;
    // 1024 float4 per row; halves of 512, 16 iterations each.
    #pragma unroll 8
    for (int i = lane; i < 512; i += 32) {
        float4 a0 = w4[i];
        float4 a1 = w4[i + 512];
        float4 b0 = v4[i];
        float4 b1 = v4[i + 512];
        acc0 += a0.x * b0.x + a0.y * b0.y + a0.z * b0.z + a0.w * b0.w;
        acc1 += a1.x * b1.x + a1.y * b1.y + a1.z * b1.z + a1.w * b1.w;
    }
    float acc = warp_sum(acc0 + acc1);
    if (lane == 0) out_hidden[r] = acc;
}

// ---------------------------------------------------------------------------
extern "C" void kernel_launch(void* const* d_in, const int* in_sizes, int n_in,
                              void* d_out, int out_size) {
    const float* hidden_in  = (const float*)d_in[0];
    const float* conv_state = (const float*)d_in[1];
    const float* rec_state  = (const float*)d_in[2];
    const float* conv_w     = (const float*)d_in[3];
    const float* qkv_w      = (const float*)d_in[4];
    const float* z_w        = (const float*)d_in[5];
    const float* b_w        = (const float*)d_in[6];
    const float* a_w        = (const float*)d_in[7];
    const float* out_proj_w = (const float*)d_in[8];
    const float* dt_bias    = (const float*)d_in[9];
    const float* A_log      = (const float*)d_in[10];
    const float* norm_w     = (const float*)d_in[11];

    float* out        = (float*)d_out;
    float* out_hidden = out;
    float* out_cs     = out + H_DIM;
    float* out_rec    = out + H_DIM + CONV_DIM * CONV_K;

    k_gemv_conv<<<(TOTAL_GEMV_ROWS + 7) / 8, 256>>>(
        hidden_in, qkv_w, z_w, b_w, a_w, conv_state, conv_w, out_cs);

    k_delta<<<NV, 512>>>(rec_state, dt_bias, A_log, norm_w, out_rec);

    k_outproj<<<H_DIM / 8, 256>>>(out_proj_w, out_hidden);
}